// round 2
// baseline (speedup 1.0000x reference)
#include <cuda_runtime.h>
#include <math.h>

// ---------------------------------------------------------------------------
// Scratch (device globals: allocation-free per harness rules)
// ---------------------------------------------------------------------------
#define NSEQ 8192
#define DMODEL 1024

__device__ float g_Q[(size_t)NSEQ * DMODEL];
__device__ float g_K[(size_t)NSEQ * DMODEL];
__device__ float g_V[(size_t)NSEQ * DMODEL];
__device__ float g_S[(size_t)NSEQ * NSEQ];

// ---------------------------------------------------------------------------
// SGEMM: C[M,N] = alpha * A[M,K] @ op(B)
//   TRANS_B = false : B is [K,N] row-major (NN)
//   TRANS_B = true  : B is [N,K] row-major, effectively B^T (NT)
// Requires M%128==0, N%128==0, K%8==0 (true for all calls here).
// 128x128 block tile, BK=8, 256 threads, 8x8 per-thread microtile.
// ---------------------------------------------------------------------------
#define BM 128
#define BN 128
#define BK 8
#define TM 8
#define TN 8

template <bool TRANS_B>
__global__ __launch_bounds__(256, 2) void sgemm_kernel(
    const float* __restrict__ A, const float* __restrict__ B,
    float* __restrict__ C, int M, int N, int K, float alpha)
{
    __shared__ float As[BK][BM];
    __shared__ float Bs[BK][BN];

    const int tid = threadIdx.x;
    const int tx  = tid & 15;        // 0..15  -> N direction
    const int ty  = tid >> 4;        // 0..15  -> M direction
    const int bm  = blockIdx.y * BM;
    const int bn  = blockIdx.x * BN;

    float acc[TM][TN];
    #pragma unroll
    for (int i = 0; i < TM; i++)
        #pragma unroll
        for (int j = 0; j < TN; j++) acc[i][j] = 0.0f;

    // A tile load mapping: 128 rows x 8 cols, one float4 per thread
    const int a_row = tid >> 1;            // 0..127
    const int a_col = (tid & 1) * 4;       // 0 or 4

    for (int k0 = 0; k0 < K; k0 += BK) {
        // ---- load A tile (transposed into As[k][m]) ----
        float4 av = *(const float4*)(A + (size_t)(bm + a_row) * K + (k0 + a_col));
        As[a_col + 0][a_row] = av.x;
        As[a_col + 1][a_row] = av.y;
        As[a_col + 2][a_row] = av.z;
        As[a_col + 3][a_row] = av.w;

        // ---- load B tile ----
        if (TRANS_B) {
            // B is [N,K]; need Bs[k][n] = B[bn+n][k0+k]
            const int r = tid >> 1;          // n: 0..127
            const int c = (tid & 1) * 4;     // k: 0 or 4
            float4 bv = *(const float4*)(B + (size_t)(bn + r) * K + (k0 + c));
            Bs[c + 0][r] = bv.x;
            Bs[c + 1][r] = bv.y;
            Bs[c + 2][r] = bv.z;
            Bs[c + 3][r] = bv.w;
        } else {
            // B is [K,N]; Bs[k][n] = B[k0+k][bn+n]
            const int r = tid >> 5;          // k: 0..7
            const int c = (tid & 31) * 4;    // n: 0..124
            float4 bv = *(const float4*)(B + (size_t)(k0 + r) * N + (bn + c));
            *(float4*)&Bs[r][c] = bv;
        }
        __syncthreads();

        // ---- compute ----
        #pragma unroll
        for (int kk = 0; kk < BK; kk++) {
            float ra[TM], rb[TN];
            #pragma unroll
            for (int i = 0; i < TM; i++) ra[i] = As[kk][ty * TM + i];
            #pragma unroll
            for (int j = 0; j < TN; j++) rb[j] = Bs[kk][tx * TN + j];
            #pragma unroll
            for (int i = 0; i < TM; i++)
                #pragma unroll
                for (int j = 0; j < TN; j++)
                    acc[i][j] = fmaf(ra[i], rb[j], acc[i][j]);
        }
        __syncthreads();
    }

    // ---- epilogue ----
    #pragma unroll
    for (int i = 0; i < TM; i++) {
        float* crow = C + (size_t)(bm + ty * TM + i) * N + (bn + tx * TN);
        #pragma unroll
        for (int j = 0; j < TN; j += 4) {
            float4 v;
            v.x = alpha * acc[i][j + 0];
            v.y = alpha * acc[i][j + 1];
            v.z = alpha * acc[i][j + 2];
            v.w = alpha * acc[i][j + 3];
            *(float4*)(crow + j) = v;
        }
    }
}

// ---------------------------------------------------------------------------
// Row softmax over S (NSEQ x NSEQ), one block per row, single read + write.
// 256 threads * 32 elems/thread = 8192.
// ---------------------------------------------------------------------------
__device__ __forceinline__ float warpReduceMax(float v) {
    #pragma unroll
    for (int o = 16; o > 0; o >>= 1) v = fmaxf(v, __shfl_xor_sync(0xFFFFFFFFu, v, o));
    return v;
}
__device__ __forceinline__ float warpReduceSum(float v) {
    #pragma unroll
    for (int o = 16; o > 0; o >>= 1) v += __shfl_xor_sync(0xFFFFFFFFu, v, o);
    return v;
}

__global__ __launch_bounds__(256) void softmax_kernel(float* __restrict__ S)
{
    const int row = blockIdx.x;
    float* p = S + (size_t)row * NSEQ;
    const int tid = threadIdx.x;
    constexpr int PER = NSEQ / 256;   // 32

    float v[PER];
    float m = -3.0e38f;
    #pragma unroll
    for (int i = 0; i < PER; i++) {
        v[i] = p[i * 256 + tid];
        m = fmaxf(m, v[i]);
    }

    __shared__ float sh[8];
    __shared__ float s_bcast;

    // ---- block max ----
    m = warpReduceMax(m);
    if ((tid & 31) == 0) sh[tid >> 5] = m;
    __syncthreads();
    if (tid < 32) {
        float bm = (tid < 8) ? sh[tid] : -3.0e38f;
        bm = warpReduceMax(bm);
        if (tid == 0) s_bcast = bm;
    }
    __syncthreads();
    m = s_bcast;

    // ---- exp + block sum ----
    float s = 0.0f;
    #pragma unroll
    for (int i = 0; i < PER; i++) {
        v[i] = __expf(v[i] - m);
        s += v[i];
    }
    s = warpReduceSum(s);
    __syncthreads();   // all reads of sh[] from the max phase are done
    if ((tid & 31) == 0) sh[tid >> 5] = s;
    __syncthreads();
    if (tid < 32) {
        float bs = (tid < 8) ? sh[tid] : 0.0f;
        bs = warpReduceSum(bs);
        if (tid == 0) s_bcast = bs;
    }
    __syncthreads();
    const float inv = 1.0f / s_bcast;

    #pragma unroll
    for (int i = 0; i < PER; i++)
        p[i * 256 + tid] = v[i] * inv;
}

// ---------------------------------------------------------------------------
// Launch
// ---------------------------------------------------------------------------
extern "C" void kernel_launch(void* const* d_in, const int* in_sizes, int n_in,
                              void* d_out, int out_size)
{
    const float* X  = (const float*)d_in[0];
    const float* Wq = (const float*)d_in[1];
    const float* Wk = (const float*)d_in[2];
    const float* Wv = (const float*)d_in[3];
    float* out = (float*)d_out;

    float *Q, *K, *V, *S;
    cudaGetSymbolAddress((void**)&Q, g_Q);
    cudaGetSymbolAddress((void**)&K, g_K);
    cudaGetSymbolAddress((void**)&V, g_V);
    cudaGetSymbolAddress((void**)&S, g_S);

    const int N = NSEQ, D = DMODEL;
    const dim3 blk(256);

    // Projections: [8192,1024] = [8192,1024] @ [1024,1024]
    const dim3 gProj(D / BN, N / BM);
    sgemm_kernel<false><<<gProj, blk>>>(X, Wq, Q, N, D, D, 1.0f);
    sgemm_kernel<false><<<gProj, blk>>>(X, Wk, K, N, D, D, 1.0f);
    sgemm_kernel<false><<<gProj, blk>>>(X, Wv, V, N, D, D, 1.0f);

    // Scores: [8192,8192] = (Q @ K^T) / 32
    const dim3 gScores(N / BN, N / BM);
    sgemm_kernel<true><<<gScores, blk>>>(Q, K, S, N, N, D, 0.03125f);

    // Softmax rows
    softmax_kernel<<<N, blk>>>(S);

    // Context: [8192,1024] = P @ V
    const dim3 gCtx(D / BN, N / BM);
    sgemm_kernel<false><<<gCtx, blk>>>(S, V, out, N, D, N, 1.0f);
}

// round 4
// speedup vs baseline: 2.8617x; 2.8617x over previous
#include <cuda_runtime.h>
#include <math.h>
#include <stdint.h>

// ===========================================================================
// Problem dims
// ===========================================================================
#define NSEQ 8192
#define DM   1024

// ===========================================================================
// Scratch (device globals — allocation-free rule)
// ===========================================================================
__device__ float g_Wt[3][(size_t)DM * DM];       // W^T  [d_out, d_in]
__device__ float g_Q [(size_t)NSEQ * DM];
__device__ float g_K [(size_t)NSEQ * DM];
__device__ float g_V [(size_t)NSEQ * DM];
__device__ float g_Vt[(size_t)DM * NSEQ];        // V^T  [d_out, N]
__device__ float g_S [(size_t)NSEQ * NSEQ];

// ===========================================================================
// Small PTX helpers
// ===========================================================================
__device__ __forceinline__ uint32_t smem_u32(const void* p) {
    uint32_t a;
    asm("{ .reg .u64 t; cvta.to.shared.u64 t, %1; cvt.u32.u64 %0, t; }"
        : "=r"(a) : "l"(p));
    return a;
}
__device__ __forceinline__ uint32_t f2tf32(float f) {
    uint32_t r;
    asm("cvt.rna.tf32.f32 %0, %1;" : "=r"(r) : "f"(f));
    return r;
}
__device__ __forceinline__ void cp_async16(uint32_t dst, const float* src) {
    asm volatile("cp.async.cg.shared.global [%0], [%1], 16;"
                 :: "r"(dst), "l"(src));
}
__device__ __forceinline__ void mma_tf32(float* c, const uint32_t* a,
                                         uint32_t b0, uint32_t b1) {
    asm volatile(
        "mma.sync.aligned.m16n8k8.row.col.f32.tf32.tf32.f32 "
        "{%0,%1,%2,%3}, {%4,%5,%6,%7}, {%8,%9}, {%0,%1,%2,%3};"
        : "+f"(c[0]), "+f"(c[1]), "+f"(c[2]), "+f"(c[3])
        : "r"(a[0]), "r"(a[1]), "r"(a[2]), "r"(a[3]), "r"(b0), "r"(b1));
}

// ===========================================================================
// TF32 GEMM (NT): C[M,N] = alpha * A[M,K] @ B[N,K]^T
//   128x128 block tile, BK=32, 256 threads (8 warps, 4x2), warp tile 32x64.
//   cp.async double-buffered smem; m16n8k8 tf32 mma; fp32 accumulate.
//   Requires M%128==0, N%128==0, K%32==0.
// ===========================================================================
#define BM 128
#define BN 128
#define BK 32
#define LDS_STRIDE 36                 // floats; 144B rows, 16B-aligned, conflict-free frags
#define BUF_FLOATS (128 * LDS_STRIDE) // 4608
#define GEMM_SMEM_BYTES (4 * BUF_FLOATS * 4)  // As0,As1,Bs0,Bs1 = 73728 B

__global__ __launch_bounds__(256, 2)
void gemm_tf32(const float* __restrict__ A, const float* __restrict__ B,
               float* __restrict__ C, int Kdim, int ldc, float alpha)
{
    extern __shared__ float smem[];
    const int tid  = threadIdx.x;
    const int lane = tid & 31;
    const int wid  = tid >> 5;
    const int warp_m = wid & 3;        // 0..3 -> M
    const int warp_n = wid >> 2;       // 0..1 -> N
    const int m0 = blockIdx.y * BM;
    const int n0 = blockIdx.x * BN;

    float* Asb[2] = { smem,                  smem + BUF_FLOATS };
    float* Bsb[2] = { smem + 2 * BUF_FLOATS, smem + 3 * BUF_FLOATS };
    uint32_t sA[2] = { smem_u32(Asb[0]), smem_u32(Asb[1]) };
    uint32_t sB[2] = { smem_u32(Bsb[0]), smem_u32(Bsb[1]) };

    float acc[2][8][4];
    #pragma unroll
    for (int mt = 0; mt < 2; mt++)
        #pragma unroll
        for (int nt = 0; nt < 8; nt++)
            #pragma unroll
            for (int j = 0; j < 4; j++) acc[mt][nt][j] = 0.0f;

    // ---- tile loader: 2048 16B chunks (A:1024, B:1024), 8 per thread ----
    auto load_tile = [&](int buf, int k0) {
        #pragma unroll
        for (int i = 0; i < 8; i++) {
            const int  c   = tid + (i & 3) * 256;   // 0..1023
            const int  row = c >> 3;                // 0..127
            const int  col = c & 7;                 // 16B chunk in row
            if (i < 4) {
                cp_async16(sA[buf] + (uint32_t)(row * 144 + col * 16),
                           A + (size_t)(m0 + row) * Kdim + k0 + col * 4);
            } else {
                cp_async16(sB[buf] + (uint32_t)(row * 144 + col * 16),
                           B + (size_t)(n0 + row) * Kdim + k0 + col * 4);
            }
        }
        asm volatile("cp.async.commit_group;");
    };

    auto compute = [&](int buf) {
        const float* as = Asb[buf];
        const float* bs = Bsb[buf];
        #pragma unroll
        for (int ks = 0; ks < 4; ks++) {           // four k8 steps
            uint32_t a[2][4];
            const int ac = ks * 8 + (lane & 3);
            const int ar = warp_m * 32 + (lane >> 2);
            #pragma unroll
            for (int mt = 0; mt < 2; mt++) {
                const float* base = as + (ar + mt * 16) * LDS_STRIDE;
                a[mt][0] = f2tf32(base[ac]);
                a[mt][1] = f2tf32(base[8 * LDS_STRIDE + ac]);
                a[mt][2] = f2tf32(base[ac + 4]);
                a[mt][3] = f2tf32(base[8 * LDS_STRIDE + ac + 4]);
            }
            #pragma unroll
            for (int nt = 0; nt < 8; nt++) {
                const int bn = warp_n * 64 + nt * 8 + (lane >> 2);
                const float* bb = bs + bn * LDS_STRIDE + ks * 8 + (lane & 3);
                const uint32_t b0 = f2tf32(bb[0]);
                const uint32_t b1 = f2tf32(bb[4]);
                mma_tf32(acc[0][nt], a[0], b0, b1);
                mma_tf32(acc[1][nt], a[1], b0, b1);
            }
        }
    };

    const int KT = Kdim / BK;
    load_tile(0, 0);
    for (int kt = 0; kt < KT; kt++) {
        if (kt + 1 < KT) {
            load_tile((kt + 1) & 1, (kt + 1) * BK);
            asm volatile("cp.async.wait_group 1;");
        } else {
            asm volatile("cp.async.wait_group 0;");
        }
        __syncthreads();
        compute(kt & 1);
        __syncthreads();
    }

    // ---- epilogue: float2 stores straight from fragments ----
    #pragma unroll
    for (int mt = 0; mt < 2; mt++) {
        const int r0 = m0 + warp_m * 32 + mt * 16 + (lane >> 2);
        #pragma unroll
        for (int nt = 0; nt < 8; nt++) {
            const int col = n0 + warp_n * 64 + nt * 8 + 2 * (lane & 3);
            float2 v0 = { alpha * acc[mt][nt][0], alpha * acc[mt][nt][1] };
            float2 v1 = { alpha * acc[mt][nt][2], alpha * acc[mt][nt][3] };
            *(float2*)(C + (size_t)r0 * ldc + col)       = v0;
            *(float2*)(C + (size_t)(r0 + 8) * ldc + col) = v1;
        }
    }
}

// ===========================================================================
// fp32 transpose: src [R,C] -> dst [C,R]
// ===========================================================================
__global__ __launch_bounds__(256) void transpose_kernel(
    const float* __restrict__ src, float* __restrict__ dst, int R, int C)
{
    __shared__ float t[32][33];
    const int tx = threadIdx.x, ty = threadIdx.y;   // block (32,8)
    const int bx = blockIdx.x * 32, by = blockIdx.y * 32;
    #pragma unroll
    for (int j = 0; j < 4; j++)
        t[ty + j * 8][tx] = src[(size_t)(by + ty + j * 8) * C + bx + tx];
    __syncthreads();
    #pragma unroll
    for (int j = 0; j < 4; j++)
        dst[(size_t)(bx + ty + j * 8) * R + by + tx] = t[tx][ty + j * 8];
}

// ===========================================================================
// Row softmax over S (NSEQ x NSEQ), in place. 256 threads, 32 elems/thread.
// ===========================================================================
__device__ __forceinline__ float wmax(float v) {
    #pragma unroll
    for (int o = 16; o > 0; o >>= 1) v = fmaxf(v, __shfl_xor_sync(0xFFFFFFFFu, v, o));
    return v;
}
__device__ __forceinline__ float wsum(float v) {
    #pragma unroll
    for (int o = 16; o > 0; o >>= 1) v += __shfl_xor_sync(0xFFFFFFFFu, v, o);
    return v;
}

__global__ __launch_bounds__(256) void softmax_kernel(float* __restrict__ S)
{
    const int row = blockIdx.x;
    float* p = S + (size_t)row * NSEQ;
    const int tid = threadIdx.x;
    constexpr int PER = NSEQ / 256;   // 32

    float v[PER];
    float m = -3.0e38f;
    #pragma unroll
    for (int i = 0; i < PER; i++) {
        v[i] = p[i * 256 + tid];
        m = fmaxf(m, v[i]);
    }

    __shared__ float sh[8];
    __shared__ float bc;

    m = wmax(m);
    if ((tid & 31) == 0) sh[tid >> 5] = m;
    __syncthreads();
    if (tid < 32) {
        float bm = (tid < 8) ? sh[tid] : -3.0e38f;
        bm = wmax(bm);
        if (tid == 0) bc = bm;
    }
    __syncthreads();
    m = bc;

    float s = 0.0f;
    #pragma unroll
    for (int i = 0; i < PER; i++) {
        v[i] = __expf(v[i] - m);
        s += v[i];
    }
    s = wsum(s);
    __syncthreads();
    if ((tid & 31) == 0) sh[tid >> 5] = s;
    __syncthreads();
    if (tid < 32) {
        float bs = (tid < 8) ? sh[tid] : 0.0f;
        bs = wsum(bs);
        if (tid == 0) bc = bs;
    }
    __syncthreads();
    const float inv = 1.0f / bc;

    #pragma unroll
    for (int i = 0; i < PER; i++)
        p[i * 256 + tid] = v[i] * inv;
}

// ===========================================================================
// Launch
// ===========================================================================
extern "C" void kernel_launch(void* const* d_in, const int* in_sizes, int n_in,
                              void* d_out, int out_size)
{
    const float* X  = (const float*)d_in[0];
    const float* Wq = (const float*)d_in[1];
    const float* Wk = (const float*)d_in[2];
    const float* Wv = (const float*)d_in[3];
    float* out = (float*)d_out;

    float *Wt, *Q, *K, *V, *Vt, *S;
    cudaGetSymbolAddress((void**)&Wt, g_Wt);
    cudaGetSymbolAddress((void**)&Q,  g_Q);
    cudaGetSymbolAddress((void**)&K,  g_K);
    cudaGetSymbolAddress((void**)&V,  g_V);
    cudaGetSymbolAddress((void**)&Vt, g_Vt);
    cudaGetSymbolAddress((void**)&S,  g_S);

    cudaFuncSetAttribute(gemm_tf32, cudaFuncAttributeMaxDynamicSharedMemorySize,
                         GEMM_SMEM_BYTES);

    const dim3 blk(256);

    // W^T (three 1024x1024 transposes)
    {
        dim3 tb(32, 8), tg(DM / 32, DM / 32);
        transpose_kernel<<<tg, tb>>>(Wq, Wt + 0 * (size_t)DM * DM, DM, DM);
        transpose_kernel<<<tg, tb>>>(Wk, Wt + 1 * (size_t)DM * DM, DM, DM);
        transpose_kernel<<<tg, tb>>>(Wv, Wt + 2 * (size_t)DM * DM, DM, DM);
    }

    // Projections: [8192,1024] = X @ Wt^T
    {
        dim3 g(DM / BN, NSEQ / BM);
        gemm_tf32<<<g, blk, GEMM_SMEM_BYTES>>>(X, Wt + 0 * (size_t)DM * DM, Q, DM, DM, 1.0f);
        gemm_tf32<<<g, blk, GEMM_SMEM_BYTES>>>(X, Wt + 1 * (size_t)DM * DM, K, DM, DM, 1.0f);
        gemm_tf32<<<g, blk, GEMM_SMEM_BYTES>>>(X, Wt + 2 * (size_t)DM * DM, V, DM, DM, 1.0f);
    }

    // V^T: [1024, 8192]
    {
        dim3 tb(32, 8), tg(DM / 32, NSEQ / 32);
        transpose_kernel<<<tg, tb>>>(V, Vt, NSEQ, DM);
    }

    // Scores: S = (Q @ K^T) / 32
    {
        dim3 g(NSEQ / BN, NSEQ / BM);
        gemm_tf32<<<g, blk, GEMM_SMEM_BYTES>>>(Q, K, S, DM, NSEQ, 0.03125f);
    }

    // Softmax rows (in place)
    softmax_kernel<<<NSEQ, blk>>>(S);

    // Context: out = P @ (V^T)^T
    {
        dim3 g(DM / BN, NSEQ / BM);
        gemm_tf32<<<g, blk, GEMM_SMEM_BYTES>>>(S, Vt, out, NSEQ, DM, 1.0f);
    }
}

// round 5
// speedup vs baseline: 3.9699x; 1.3873x over previous
#include <cuda_runtime.h>
#include <math.h>
#include <stdint.h>

// ===========================================================================
// Problem dims
// ===========================================================================
#define NSEQ 8192
#define DM   1024

// ===========================================================================
// Scratch (device globals — allocation-free rule)
// ===========================================================================
__device__ float g_Xr[(size_t)NSEQ * DM];        // X rounded to tf32
__device__ float g_Wt[3][(size_t)DM * DM];       // W^T rounded  [d_out, d_in]
__device__ float g_Q [(size_t)NSEQ * DM];        // rounded by epilogue
__device__ float g_K [(size_t)NSEQ * DM];        // rounded by epilogue
__device__ float g_V [(size_t)NSEQ * DM];        // fp32
__device__ float g_Vt[(size_t)DM * NSEQ];        // V^T rounded
__device__ float g_S [(size_t)NSEQ * NSEQ];      // fp32 scores; P rounded by softmax

// ===========================================================================
// Small PTX helpers
// ===========================================================================
__device__ __forceinline__ uint32_t smem_u32(const void* p) {
    uint32_t a;
    asm("{ .reg .u64 t; cvta.to.shared.u64 t, %1; cvt.u32.u64 %0, t; }"
        : "=r"(a) : "l"(p));
    return a;
}
__device__ __forceinline__ float f2tf32f(float f) {
    uint32_t r;
    asm("cvt.rna.tf32.f32 %0, %1;" : "=r"(r) : "f"(f));
    return __uint_as_float(r);
}
__device__ __forceinline__ void cp_async16(uint32_t dst, const float* src) {
    asm volatile("cp.async.cg.shared.global [%0], [%1], 16;"
                 :: "r"(dst), "l"(src));
}
__device__ __forceinline__ void ldsm_x4(uint32_t* r, uint32_t addr) {
    asm volatile("ldmatrix.sync.aligned.m8n8.x4.shared.b16 {%0,%1,%2,%3}, [%4];"
                 : "=r"(r[0]), "=r"(r[1]), "=r"(r[2]), "=r"(r[3]) : "r"(addr));
}
__device__ __forceinline__ void mma_tf32(float* c, const uint32_t* a,
                                         uint32_t b0, uint32_t b1) {
    asm volatile(
        "mma.sync.aligned.m16n8k8.row.col.f32.tf32.tf32.f32 "
        "{%0,%1,%2,%3}, {%4,%5,%6,%7}, {%8,%9}, {%0,%1,%2,%3};"
        : "+f"(c[0]), "+f"(c[1]), "+f"(c[2]), "+f"(c[3])
        : "r"(a[0]), "r"(a[1]), "r"(a[2]), "r"(a[3]), "r"(b0), "r"(b1));
}

// ===========================================================================
// TF32 GEMM (NT): C[M,N] = alpha * A[M,K] @ B[N,K]^T
//   Inputs MUST already be tf32-rounded fp32 (no cvt in the hot loop).
//   128x128 block tile, BK=32, 256 threads (8 warps, 4x2), warp tile 32x64.
//   cp.async double buffer; ldmatrix.x4 fragment loads; m16n8k8 tf32 mma.
//   ROUND_OUT: epilogue stores tf32-rounded values (for Q/K).
// ===========================================================================
#define BM 128
#define BN 128
#define BK 32
#define LDS_STRIDE 36                 // floats; 144B rows; ldmatrix conflict-free
#define BUF_FLOATS (128 * LDS_STRIDE) // 4608
#define GEMM_SMEM_BYTES (4 * BUF_FLOATS * 4)  // 73728 B

template <bool ROUND_OUT>
__global__ __launch_bounds__(256, 2)
void gemm_tf32(const float* __restrict__ A, const float* __restrict__ B,
               float* __restrict__ C, int Kdim, int ldc, float alpha)
{
    extern __shared__ float smem[];
    const int tid  = threadIdx.x;
    const int lane = tid & 31;
    const int wid  = tid >> 5;
    const int warp_m = wid & 3;        // 0..3 -> M
    const int warp_n = wid >> 2;       // 0..1 -> N
    const int m0 = blockIdx.y * BM;
    const int n0 = blockIdx.x * BN;

    uint32_t sA[2] = { smem_u32(smem),                  smem_u32(smem + BUF_FLOATS) };
    uint32_t sB[2] = { smem_u32(smem + 2 * BUF_FLOATS), smem_u32(smem + 3 * BUF_FLOATS) };

    float acc[2][8][4];
    #pragma unroll
    for (int mt = 0; mt < 2; mt++)
        #pragma unroll
        for (int nt = 0; nt < 8; nt++)
            #pragma unroll
            for (int j = 0; j < 4; j++) acc[mt][nt][j] = 0.0f;

    // ---- ldmatrix per-lane address offsets (bytes), computed once ----
    // A x4 quadrants: q0 (row+0,k+0) q1 (row+8,k+0) q2 (row+0,k+4) q3 (row+8,k+4)
    const int q  = lane >> 3;
    const int r8 = lane & 7;
    const uint32_t aOff =
        (uint32_t)(((warp_m * 32 + r8 + (q & 1) * 8) * LDS_STRIDE + (q >> 1) * 4) * 4);
    // B x4 quadrants for nt pair: q0 (nt,klo) q1 (nt,khi) q2 (nt+1,klo) q3 (nt+1,khi)
    const uint32_t bOff =
        (uint32_t)(((warp_n * 64 + (q >> 1) * 8 + r8) * LDS_STRIDE + (q & 1) * 4) * 4);

    // ---- tile loader: 2048 16B chunks (A:1024, B:1024), 8 per thread ----
    auto load_tile = [&](int buf, int k0) {
        #pragma unroll
        for (int i = 0; i < 8; i++) {
            const int  c   = tid + (i & 3) * 256;   // 0..1023
            const int  row = c >> 3;                // 0..127
            const int  col = c & 7;                 // 16B chunk in row
            if (i < 4) {
                cp_async16(sA[buf] + (uint32_t)(row * 144 + col * 16),
                           A + (size_t)(m0 + row) * Kdim + k0 + col * 4);
            } else {
                cp_async16(sB[buf] + (uint32_t)(row * 144 + col * 16),
                           B + (size_t)(n0 + row) * Kdim + k0 + col * 4);
            }
        }
        asm volatile("cp.async.commit_group;");
    };

    auto compute = [&](int buf) {
        #pragma unroll
        for (int ks = 0; ks < 4; ks++) {           // four k8 steps
            uint32_t a[2][4];
            #pragma unroll
            for (int mt = 0; mt < 2; mt++)
                ldsm_x4(a[mt], sA[buf] + aOff
                               + (uint32_t)(mt * 16 * LDS_STRIDE * 4 + ks * 32));
            #pragma unroll
            for (int ntp = 0; ntp < 4; ntp++) {    // nt pairs
                uint32_t b[4];
                ldsm_x4(b, sB[buf] + bOff
                           + (uint32_t)(ntp * 16 * LDS_STRIDE * 4 + ks * 32));
                mma_tf32(acc[0][ntp * 2 + 0], a[0], b[0], b[1]);
                mma_tf32(acc[1][ntp * 2 + 0], a[1], b[0], b[1]);
                mma_tf32(acc[0][ntp * 2 + 1], a[0], b[2], b[3]);
                mma_tf32(acc[1][ntp * 2 + 1], a[1], b[2], b[3]);
            }
        }
    };

    const int KT = Kdim / BK;
    load_tile(0, 0);
    for (int kt = 0; kt < KT; kt++) {
        if (kt + 1 < KT) {
            load_tile((kt + 1) & 1, (kt + 1) * BK);
            asm volatile("cp.async.wait_group 1;");
        } else {
            asm volatile("cp.async.wait_group 0;");
        }
        __syncthreads();
        compute(kt & 1);
        __syncthreads();
    }

    // ---- epilogue: float2 stores straight from fragments ----
    #pragma unroll
    for (int mt = 0; mt < 2; mt++) {
        const int r0 = m0 + warp_m * 32 + mt * 16 + (lane >> 2);
        #pragma unroll
        for (int nt = 0; nt < 8; nt++) {
            const int col = n0 + warp_n * 64 + nt * 8 + 2 * (lane & 3);
            float v[4];
            #pragma unroll
            for (int j = 0; j < 4; j++) {
                v[j] = alpha * acc[mt][nt][j];
                if (ROUND_OUT) v[j] = f2tf32f(v[j]);
            }
            *(float2*)(C + (size_t)r0 * ldc + col)       = make_float2(v[0], v[1]);
            *(float2*)(C + (size_t)(r0 + 8) * ldc + col) = make_float2(v[2], v[3]);
        }
    }
}

// ===========================================================================
// Elementwise tf32 rounding: dst = round_tf32(src)
// ===========================================================================
__global__ __launch_bounds__(256) void round_kernel(
    const float* __restrict__ src, float* __restrict__ dst, int n4)
{
    int i = blockIdx.x * 256 + threadIdx.x;
    if (i >= n4) return;
    float4 v = *(const float4*)(src + (size_t)i * 4);
    v.x = f2tf32f(v.x); v.y = f2tf32f(v.y);
    v.z = f2tf32f(v.z); v.w = f2tf32f(v.w);
    *(float4*)(dst + (size_t)i * 4) = v;
}

// ===========================================================================
// fp32 transpose: src [R,C] -> dst [C,R], optional tf32 rounding
// ===========================================================================
template <bool ROUND>
__global__ __launch_bounds__(256) void transpose_kernel(
    const float* __restrict__ src, float* __restrict__ dst, int R, int C)
{
    __shared__ float t[32][33];
    const int tx = threadIdx.x, ty = threadIdx.y;   // block (32,8)
    const int bx = blockIdx.x * 32, by = blockIdx.y * 32;
    #pragma unroll
    for (int j = 0; j < 4; j++)
        t[ty + j * 8][tx] = src[(size_t)(by + ty + j * 8) * C + bx + tx];
    __syncthreads();
    #pragma unroll
    for (int j = 0; j < 4; j++) {
        float v = t[tx][ty + j * 8];
        if (ROUND) v = f2tf32f(v);
        dst[(size_t)(bx + ty + j * 8) * R + by + tx] = v;
    }
}

// ===========================================================================
// Row softmax over S (in place), output tf32-rounded P.
// ===========================================================================
__device__ __forceinline__ float wmax(float v) {
    #pragma unroll
    for (int o = 16; o > 0; o >>= 1) v = fmaxf(v, __shfl_xor_sync(0xFFFFFFFFu, v, o));
    return v;
}
__device__ __forceinline__ float wsum(float v) {
    #pragma unroll
    for (int o = 16; o > 0; o >>= 1) v += __shfl_xor_sync(0xFFFFFFFFu, v, o);
    return v;
}

__global__ __launch_bounds__(256) void softmax_kernel(float* __restrict__ S)
{
    const int row = blockIdx.x;
    float* p = S + (size_t)row * NSEQ;
    const int tid = threadIdx.x;
    constexpr int PER = NSEQ / 256;   // 32

    float v[PER];
    float m = -3.0e38f;
    #pragma unroll
    for (int i = 0; i < PER; i++) {
        v[i] = p[i * 256 + tid];
        m = fmaxf(m, v[i]);
    }

    __shared__ float sh[8];
    __shared__ float bc;

    m = wmax(m);
    if ((tid & 31) == 0) sh[tid >> 5] = m;
    __syncthreads();
    if (tid < 32) {
        float bm = (tid < 8) ? sh[tid] : -3.0e38f;
        bm = wmax(bm);
        if (tid == 0) bc = bm;
    }
    __syncthreads();
    m = bc;

    float s = 0.0f;
    #pragma unroll
    for (int i = 0; i < PER; i++) {
        v[i] = __expf(v[i] - m);
        s += v[i];
    }
    s = wsum(s);
    __syncthreads();
    if ((tid & 31) == 0) sh[tid >> 5] = s;
    __syncthreads();
    if (tid < 32) {
        float bs = (tid < 8) ? sh[tid] : 0.0f;
        bs = wsum(bs);
        if (tid == 0) bc = bs;
    }
    __syncthreads();
    const float inv = 1.0f / bc;

    #pragma unroll
    for (int i = 0; i < PER; i++)
        p[i * 256 + tid] = f2tf32f(v[i] * inv);
}

// ===========================================================================
// Launch
// ===========================================================================
extern "C" void kernel_launch(void* const* d_in, const int* in_sizes, int n_in,
                              void* d_out, int out_size)
{
    const float* X  = (const float*)d_in[0];
    const float* Wq = (const float*)d_in[1];
    const float* Wk = (const float*)d_in[2];
    const float* Wv = (const float*)d_in[3];
    float* out = (float*)d_out;

    float *Xr, *Wt, *Q, *K, *V, *Vt, *S;
    cudaGetSymbolAddress((void**)&Xr, g_Xr);
    cudaGetSymbolAddress((void**)&Wt, g_Wt);
    cudaGetSymbolAddress((void**)&Q,  g_Q);
    cudaGetSymbolAddress((void**)&K,  g_K);
    cudaGetSymbolAddress((void**)&V,  g_V);
    cudaGetSymbolAddress((void**)&Vt, g_Vt);
    cudaGetSymbolAddress((void**)&S,  g_S);

    cudaFuncSetAttribute(gemm_tf32<false>, cudaFuncAttributeMaxDynamicSharedMemorySize,
                         GEMM_SMEM_BYTES);
    cudaFuncSetAttribute(gemm_tf32<true>, cudaFuncAttributeMaxDynamicSharedMemorySize,
                         GEMM_SMEM_BYTES);

    const dim3 blk(256);

    // X rounded; W^T rounded
    round_kernel<<<(NSEQ * DM / 4 + 255) / 256, blk>>>(X, Xr, NSEQ * DM / 4);
    {
        dim3 tb(32, 8), tg(DM / 32, DM / 32);
        transpose_kernel<true><<<tg, tb>>>(Wq, Wt + 0 * (size_t)DM * DM, DM, DM);
        transpose_kernel<true><<<tg, tb>>>(Wk, Wt + 1 * (size_t)DM * DM, DM, DM);
        transpose_kernel<true><<<tg, tb>>>(Wv, Wt + 2 * (size_t)DM * DM, DM, DM);
    }

    // Projections: Q,K rounded for scores GEMM; V fp32 (rounded at transpose)
    {
        dim3 g(DM / BN, NSEQ / BM);
        gemm_tf32<true ><<<g, blk, GEMM_SMEM_BYTES>>>(Xr, Wt + 0 * (size_t)DM * DM, Q, DM, DM, 1.0f);
        gemm_tf32<true ><<<g, blk, GEMM_SMEM_BYTES>>>(Xr, Wt + 1 * (size_t)DM * DM, K, DM, DM, 1.0f);
        gemm_tf32<false><<<g, blk, GEMM_SMEM_BYTES>>>(Xr, Wt + 2 * (size_t)DM * DM, V, DM, DM, 1.0f);
    }

    // V^T rounded: [1024, 8192]
    {
        dim3 tb(32, 8), tg(DM / 32, NSEQ / 32);
        transpose_kernel<true><<<tg, tb>>>(V, Vt, NSEQ, DM);
    }

    // Scores: S = (Q @ K^T) / 32   (fp32 out)
    {
        dim3 g(NSEQ / BN, NSEQ / BM);
        gemm_tf32<false><<<g, blk, GEMM_SMEM_BYTES>>>(Q, K, S, DM, NSEQ, 0.03125f);
    }

    // Softmax rows (in place), P tf32-rounded
    softmax_kernel<<<NSEQ, blk>>>(S);

    // Context: out = P @ (V^T)^T   (fp32 out)
    {
        dim3 g(DM / BN, NSEQ / BM);
        gemm_tf32<false><<<g, blk, GEMM_SMEM_BYTES>>>(S, Vt, out, NSEQ, DM, 1.0f);
    }
}

// round 7
// speedup vs baseline: 4.7223x; 1.1895x over previous
#include <cuda_runtime.h>
#include <math.h>
#include <stdint.h>

// ===========================================================================
// Problem dims
// ===========================================================================
#define NSEQ 8192
#define DM   1024

// ===========================================================================
// Scratch (device globals — allocation-free rule)
// ===========================================================================
__device__ float g_Xr[(size_t)NSEQ * DM];        // X rounded to tf32
__device__ float g_Wt[3][(size_t)DM * DM];       // W^T rounded  [d_out, d_in]
__device__ float g_Q [(size_t)NSEQ * DM];        // rounded by epilogue
__device__ float g_K [(size_t)NSEQ * DM];        // rounded by epilogue
__device__ float g_V [(size_t)NSEQ * DM];        // fp32
__device__ float g_Vt[(size_t)DM * NSEQ];        // V^T rounded
__device__ float g_P [(size_t)NSEQ * NSEQ];      // exp(scores), tf32-rounded
__device__ float g_psum[64 * (size_t)NSEQ];      // per-n-tile partial row sums
__device__ float g_rowsum[NSEQ];

// ===========================================================================
// Small PTX helpers
// ===========================================================================
__device__ __forceinline__ uint32_t smem_u32(const void* p) {
    uint32_t a;
    asm("{ .reg .u64 t; cvta.to.shared.u64 t, %1; cvt.u32.u64 %0, t; }"
        : "=r"(a) : "l"(p));
    return a;
}
__device__ __forceinline__ float f2tf32f(float f) {
    uint32_t r;
    asm("cvt.rna.tf32.f32 %0, %1;" : "=r"(r) : "f"(f));
    return __uint_as_float(r);
}
__device__ __forceinline__ void cp_async16(uint32_t dst, const float* src) {
    asm volatile("cp.async.cg.shared.global [%0], [%1], 16;"
                 :: "r"(dst), "l"(src));
}
__device__ __forceinline__ void ldsm_x4(uint32_t* r, uint32_t addr) {
    asm volatile("ldmatrix.sync.aligned.m8n8.x4.shared.b16 {%0,%1,%2,%3}, [%4];"
                 : "=r"(r[0]), "=r"(r[1]), "=r"(r[2]), "=r"(r[3]) : "r"(addr));
}
__device__ __forceinline__ void mma_tf32(float* c, const uint32_t* a,
                                         uint32_t b0, uint32_t b1) {
    asm volatile(
        "mma.sync.aligned.m16n8k8.row.col.f32.tf32.tf32.f32 "
        "{%0,%1,%2,%3}, {%4,%5,%6,%7}, {%8,%9}, {%0,%1,%2,%3};"
        : "+f"(c[0]), "+f"(c[1]), "+f"(c[2]), "+f"(c[3])
        : "r"(a[0]), "r"(a[1]), "r"(a[2]), "r"(a[3]), "r"(b0), "r"(b1));
}

// ===========================================================================
// TF32 GEMM (NT): C[M,N] = op( alpha * A[M,K] @ B[N,K]^T )
//   Inputs MUST already be tf32-rounded fp32.
//   128x128 block tile, BK=32, 256 threads (8 warps, 4x2), warp tile 32x64.
//   3-stage cp.async pipeline, one __syncthreads per k-iter.
//   EPI: 0 = alpha*acc           (fp32 out)
//        1 = round_tf32(acc)     (alpha=1; Q/K)
//        2 = round_tf32(exp(alpha*acc)) + deterministic partial row sums
//        3 = acc / rowsum[row]
// ===========================================================================
#define BM 128
#define BN 128
#define BK 32
#define STAGES 3
#define LDS_STRIDE 36                 // floats; 144B rows; ldmatrix conflict-free
#define BUF_FLOATS (128 * LDS_STRIDE) // 4608
#define GEMM_SMEM_BYTES (2 * STAGES * BUF_FLOATS * 4)  // 110592 B

template <int EPI>
__global__ __launch_bounds__(256, 2)
void gemm_tf32(const float* __restrict__ A, const float* __restrict__ B,
               float* __restrict__ C, int Kdim, int ldc, float alpha,
               float* __restrict__ psum, const float* __restrict__ rowsum)
{
    extern __shared__ float smem[];
    const int tid  = threadIdx.x;
    const int lane = tid & 31;
    const int wid  = tid >> 5;
    const int warp_m = wid & 3;        // 0..3 -> M
    const int warp_n = wid >> 2;       // 0..1 -> N
    const int m0 = blockIdx.y * BM;
    const int n0 = blockIdx.x * BN;

    uint32_t sA[STAGES], sB[STAGES];
    #pragma unroll
    for (int s = 0; s < STAGES; s++) {
        sA[s] = smem_u32(smem + (2 * s + 0) * BUF_FLOATS);
        sB[s] = smem_u32(smem + (2 * s + 1) * BUF_FLOATS);
    }

    float acc[2][8][4];
    #pragma unroll
    for (int mt = 0; mt < 2; mt++)
        #pragma unroll
        for (int nt = 0; nt < 8; nt++)
            #pragma unroll
            for (int j = 0; j < 4; j++) acc[mt][nt][j] = 0.0f;

    // ---- ldmatrix per-lane address offsets (bytes) ----
    const int q  = lane >> 3;
    const int r8 = lane & 7;
    const uint32_t aOff =
        (uint32_t)(((warp_m * 32 + r8 + (q & 1) * 8) * LDS_STRIDE + (q >> 1) * 4) * 4);
    const uint32_t bOff =
        (uint32_t)(((warp_n * 64 + (q >> 1) * 8 + r8) * LDS_STRIDE + (q & 1) * 4) * 4);

    auto load_tile = [&](int buf, int k0) {
        #pragma unroll
        for (int i = 0; i < 8; i++) {
            const int  c   = tid + (i & 3) * 256;   // 0..1023
            const int  row = c >> 3;                // 0..127
            const int  col = c & 7;                 // 16B chunk in row
            if (i < 4) {
                cp_async16(sA[buf] + (uint32_t)(row * 144 + col * 16),
                           A + (size_t)(m0 + row) * Kdim + k0 + col * 4);
            } else {
                cp_async16(sB[buf] + (uint32_t)(row * 144 + col * 16),
                           B + (size_t)(n0 + row) * Kdim + k0 + col * 4);
            }
        }
        asm volatile("cp.async.commit_group;");
    };

    auto compute = [&](int buf) {
        #pragma unroll
        for (int ks = 0; ks < 4; ks++) {           // four k8 steps
            uint32_t a[2][4];
            #pragma unroll
            for (int mt = 0; mt < 2; mt++)
                ldsm_x4(a[mt], sA[buf] + aOff
                               + (uint32_t)(mt * 16 * LDS_STRIDE * 4 + ks * 32));
            #pragma unroll
            for (int ntp = 0; ntp < 4; ntp++) {    // nt pairs
                uint32_t b[4];
                ldsm_x4(b, sB[buf] + bOff
                           + (uint32_t)(ntp * 16 * LDS_STRIDE * 4 + ks * 32));
                mma_tf32(acc[0][ntp * 2 + 0], a[0], b[0], b[1]);
                mma_tf32(acc[1][ntp * 2 + 0], a[1], b[0], b[1]);
                mma_tf32(acc[0][ntp * 2 + 1], a[0], b[2], b[3]);
                mma_tf32(acc[1][ntp * 2 + 1], a[1], b[2], b[3]);
            }
        }
    };

    const int KT = Kdim / BK;
    load_tile(0, 0);
    load_tile(1, BK);
    for (int kt = 0; kt < KT; kt++) {
        if (kt + 2 < KT) {
            asm volatile("cp.async.wait_group 1;");
        } else {
            asm volatile("cp.async.wait_group 0;");
        }
        __syncthreads();
        compute(kt % STAGES);
        if (kt + 2 < KT) load_tile((kt + 2) % STAGES, (kt + 2) * BK);
    }
    __syncthreads();   // before smem reuse in EPI==2

    // ---- epilogue ----
    float rs[2][2];
    rs[0][0] = rs[0][1] = rs[1][0] = rs[1][1] = 0.0f;

    #pragma unroll
    for (int mt = 0; mt < 2; mt++) {
        const int r0 = m0 + warp_m * 32 + mt * 16 + (lane >> 2);
        float inv0 = 1.0f, inv1 = 1.0f;
        if (EPI == 3) {
            inv0 = 1.0f / rowsum[r0];
            inv1 = 1.0f / rowsum[r0 + 8];
        }
        #pragma unroll
        for (int nt = 0; nt < 8; nt++) {
            const int col = n0 + warp_n * 64 + nt * 8 + 2 * (lane & 3);
            float v[4];
            #pragma unroll
            for (int j = 0; j < 4; j++) v[j] = acc[mt][nt][j];
            if (EPI == 0) {
                #pragma unroll
                for (int j = 0; j < 4; j++) v[j] *= alpha;
            } else if (EPI == 1) {
                #pragma unroll
                for (int j = 0; j < 4; j++) v[j] = f2tf32f(v[j]);
            } else if (EPI == 2) {
                #pragma unroll
                for (int j = 0; j < 4; j++) v[j] = __expf(alpha * v[j]);
                rs[mt][0] += v[0] + v[1];
                rs[mt][1] += v[2] + v[3];
                #pragma unroll
                for (int j = 0; j < 4; j++) v[j] = f2tf32f(v[j]);
            } else { // EPI == 3
                v[0] *= inv0; v[1] *= inv0;
                v[2] *= inv1; v[3] *= inv1;
            }
            *(float2*)(C + (size_t)r0 * ldc + col)       = make_float2(v[0], v[1]);
            *(float2*)(C + (size_t)(r0 + 8) * ldc + col) = make_float2(v[2], v[3]);
        }
    }

    if (EPI == 2) {
        // deterministic partial row sums: reduce over lane&3, then over warp_n
        #pragma unroll
        for (int mt = 0; mt < 2; mt++)
            #pragma unroll
            for (int h = 0; h < 2; h++) {
                rs[mt][h] += __shfl_xor_sync(0xFFFFFFFFu, rs[mt][h], 1);
                rs[mt][h] += __shfl_xor_sync(0xFFFFFFFFu, rs[mt][h], 2);
            }
        float* spart = smem;   // [2][128]
        if ((lane & 3) == 0) {
            const int rb = warp_m * 32 + (lane >> 2);
            spart[warp_n * 128 + rb + 0]  = rs[0][0];
            spart[warp_n * 128 + rb + 8]  = rs[0][1];
            spart[warp_n * 128 + rb + 16] = rs[1][0];
            spart[warp_n * 128 + rb + 24] = rs[1][1];
        }
        __syncthreads();
        if (tid < 128)
            psum[(size_t)blockIdx.x * NSEQ + m0 + tid] = spart[tid] + spart[128 + tid];
    }
}

// ===========================================================================
// Row-sum reduction: rowsum[r] = sum_t psum[t][r]
// ===========================================================================
__global__ __launch_bounds__(256) void rowsum_kernel(
    const float* __restrict__ psum, float* __restrict__ rowsum)
{
    const int r = blockIdx.x * 256 + threadIdx.x;
    float s = 0.0f;
    #pragma unroll 8
    for (int t = 0; t < NSEQ / BN; t++) s += psum[(size_t)t * NSEQ + r];
    rowsum[r] = s;
}

// ===========================================================================
// Elementwise tf32 rounding
// ===========================================================================
__global__ __launch_bounds__(256) void round_kernel(
    const float* __restrict__ src, float* __restrict__ dst, int n4)
{
    int i = blockIdx.x * 256 + threadIdx.x;
    if (i >= n4) return;
    float4 v = *(const float4*)(src + (size_t)i * 4);
    v.x = f2tf32f(v.x); v.y = f2tf32f(v.y);
    v.z = f2tf32f(v.z); v.w = f2tf32f(v.w);
    *(float4*)(dst + (size_t)i * 4) = v;
}

// ===========================================================================
// fp32 transpose: src [R,C] -> dst [C,R], optional tf32 rounding
// ===========================================================================
template <bool ROUND>
__global__ __launch_bounds__(256) void transpose_kernel(
    const float* __restrict__ src, float* __restrict__ dst, int R, int C)
{
    __shared__ float t[32][33];
    const int tx = threadIdx.x, ty = threadIdx.y;   // block (32,8)
    const int bx = blockIdx.x * 32, by = blockIdx.y * 32;
    #pragma unroll
    for (int j = 0; j < 4; j++)
        t[ty + j * 8][tx] = src[(size_t)(by + ty + j * 8) * C + bx + tx];
    __syncthreads();
    #pragma unroll
    for (int j = 0; j < 4; j++) {
        float v = t[tx][ty + j * 8];
        if (ROUND) v = f2tf32f(v);
        dst[(size_t)(bx + ty + j * 8) * R + by + tx] = v;
    }
}

// ===========================================================================
// Launch
// ===========================================================================
extern "C" void kernel_launch(void* const* d_in, const int* in_sizes, int n_in,
                              void* d_out, int out_size)
{
    const float* X  = (const float*)d_in[0];
    const float* Wq = (const float*)d_in[1];
    const float* Wk = (const float*)d_in[2];
    const float* Wv = (const float*)d_in[3];
    float* out = (float*)d_out;

    float *Xr, *Wt, *Q, *K, *V, *Vt, *P, *psum, *rowsum;
    cudaGetSymbolAddress((void**)&Xr, g_Xr);
    cudaGetSymbolAddress((void**)&Wt, g_Wt);
    cudaGetSymbolAddress((void**)&Q,  g_Q);
    cudaGetSymbolAddress((void**)&K,  g_K);
    cudaGetSymbolAddress((void**)&V,  g_V);
    cudaGetSymbolAddress((void**)&Vt, g_Vt);
    cudaGetSymbolAddress((void**)&P,  g_P);
    cudaGetSymbolAddress((void**)&psum,   g_psum);
    cudaGetSymbolAddress((void**)&rowsum, g_rowsum);

    cudaFuncSetAttribute(gemm_tf32<0>, cudaFuncAttributeMaxDynamicSharedMemorySize, GEMM_SMEM_BYTES);
    cudaFuncSetAttribute(gemm_tf32<1>, cudaFuncAttributeMaxDynamicSharedMemorySize, GEMM_SMEM_BYTES);
    cudaFuncSetAttribute(gemm_tf32<2>, cudaFuncAttributeMaxDynamicSharedMemorySize, GEMM_SMEM_BYTES);
    cudaFuncSetAttribute(gemm_tf32<3>, cudaFuncAttributeMaxDynamicSharedMemorySize, GEMM_SMEM_BYTES);

    const dim3 blk(256);

    // X rounded; W^T rounded
    round_kernel<<<(NSEQ * DM / 4 + 255) / 256, blk>>>(X, Xr, NSEQ * DM / 4);
    {
        dim3 tb(32, 8), tg(DM / 32, DM / 32);
        transpose_kernel<true><<<tg, tb>>>(Wq, Wt + 0 * (size_t)DM * DM, DM, DM);
        transpose_kernel<true><<<tg, tb>>>(Wk, Wt + 1 * (size_t)DM * DM, DM, DM);
        transpose_kernel<true><<<tg, tb>>>(Wv, Wt + 2 * (size_t)DM * DM, DM, DM);
    }

    // Projections
    {
        dim3 g(DM / BN, NSEQ / BM);
        gemm_tf32<1><<<g, blk, GEMM_SMEM_BYTES>>>(Xr, Wt + 0 * (size_t)DM * DM, Q, DM, DM, 1.0f, nullptr, nullptr);
        gemm_tf32<1><<<g, blk, GEMM_SMEM_BYTES>>>(Xr, Wt + 1 * (size_t)DM * DM, K, DM, DM, 1.0f, nullptr, nullptr);
        gemm_tf32<0><<<g, blk, GEMM_SMEM_BYTES>>>(Xr, Wt + 2 * (size_t)DM * DM, V, DM, DM, 1.0f, nullptr, nullptr);
    }

    // V^T rounded
    {
        dim3 tb(32, 8), tg(DM / 32, NSEQ / 32);
        transpose_kernel<true><<<tg, tb>>>(V, Vt, NSEQ, DM);
    }

    // P = exp(Q@K^T / 32) (tf32-rounded) + partial row sums
    {
        dim3 g(NSEQ / BN, NSEQ / BM);
        gemm_tf32<2><<<g, blk, GEMM_SMEM_BYTES>>>(Q, K, P, DM, NSEQ, 0.03125f, psum, nullptr);
    }

    // Row sums
    rowsum_kernel<<<NSEQ / 256, blk>>>(psum, rowsum);

    // out = (P @ (V^T)^T) / rowsum
    {
        dim3 g(DM / BN, NSEQ / BM);
        gemm_tf32<3><<<g, blk, GEMM_SMEM_BYTES>>>(P, Vt, out, NSEQ, DM, 1.0f, nullptr, rowsum);
    }
}